// round 16
// baseline (speedup 1.0000x reference)
#include <cuda_runtime.h>
#include <cuda_fp16.h>
#include <cstdint>

// CapsuleLayer dynamic routing, algebraically collapsed (u_hat never built):
//   L[n,m] = x[n,:] @ Pacc[:,m]  (Pacc = log2e * accum W@v, so exp == EX2)
//   E = 2^(L - bnd + 15), Z[m] = sum_n E, y[m,:] = E^T x
//   s = (y/Z) W, v = squash(s), Pacc += log2e W v
// bnd = Cauchy-Schwarz bound ||Pacc_col||*max||x_n||; +15 shift keeps fp16 E
// in range. Both GEMMs on tensor cores (mma.m16n8k16, C->A fragment reuse,
// P split hi+lo fp16).
// R16: 640 threads / 20 warps (5 per SMSP, 102-reg budget — midpoint between
// R13's 16 warps@109regs and R14's spilled 24w@80regs). Single y-accum to
// save regs. ksteps split 7/6 across warps.

#define NROW    2048
#define XSH     24            // halves per x row (48B: 16B-aligned, conflict-free)
#define THREADS 640
#define NWARP   20
#define LOG2E   1.4426950408889634f

typedef unsigned long long ull;
typedef unsigned int uint;

struct Smem {
  __half xs[NROW * XSH];        // fp16 x rows, 96KB
  float  Wdc[4096];             // [ml][d][c]
  float  Wcd[4096];             // [ml][c][d]
  float  Pacc[16][16];          // fp32 master (log2e-scaled)
  __half Pt_hi[16][XSH];        // P^T fp16 high part  [cap][d]
  __half Pt_lo[16][XSH];        // P^T fp16 residual
  float  party[NWARP][16][16];  // [warp][cap][d] partial y
  float  partZ[NWARP][16];      // [warp][cap]
  float  yfull[16][16];
  float  Zfull[16];
  float  wpart[NWARP][16];
  float  wmax[NWARP];
  float  sumx[16];
  float  vbuf[16][16];
  float  bnd[16];               // log2-domain bound per cap
  float  mxnorm;
  float  pad[3];
};

__device__ __forceinline__ float ex2f(float x) {
  float r; asm("ex2.approx.f32 %0, %1;" : "=f"(r) : "f"(x)); return r;
}
__device__ __forceinline__ uint cvt2h(float hi, float lo) {
  uint r; asm("cvt.rn.f16x2.f32 %0, %1, %2;" : "=r"(r) : "f"(hi), "f"(lo)); return r;
}
__device__ __forceinline__ void hmma(float& d0, float& d1, float& d2, float& d3,
                                     uint a0, uint a1, uint a2, uint a3,
                                     uint b0, uint b1) {
  asm("mma.sync.aligned.m16n8k16.row.col.f32.f16.f16.f32 "
      "{%0,%1,%2,%3}, {%4,%5,%6,%7}, {%8,%9}, {%0,%1,%2,%3};"
      : "+f"(d0), "+f"(d1), "+f"(d2), "+f"(d3)
      : "r"(a0), "r"(a1), "r"(a2), "r"(a3), "r"(b0), "r"(b1));
}
__device__ __forceinline__ void ldsm4t(uint& r0, uint& r1, uint& r2, uint& r3,
                                       uint addr) {
  asm volatile("ldmatrix.sync.aligned.m8n8.x4.trans.shared.b16 {%0,%1,%2,%3}, [%4];"
               : "=r"(r0), "=r"(r1), "=r"(r2), "=r"(r3) : "r"(addr));
}

__global__ void __launch_bounds__(THREADS, 1)
caps_routing_kernel(const float* __restrict__ X, const float* __restrict__ Wg,
                    float* __restrict__ Y) {
  extern __shared__ char smraw[];
  Smem* sm = reinterpret_cast<Smem*>(smraw);
  const int tid  = threadIdx.x;
  const int lane = tid & 31;
  const int w    = tid >> 5;
  const int b    = blockIdx.x >> 1;
  const int m0   = (blockIdx.x & 1) * 16;

  if (tid < 256) ((float*)sm->Pacc)[tid] = 0.f;
  if (tid >= 256 && tid < 272) sm->bnd[tid - 256] = 0.f;

  // ---- Load x tile; fp16 into smem; fold in column sums + max row norm ----
  // 8192 float4 over 640 threads: tid<512 do 13 trips, else 12 (warp-uniform).
  const float4* Xb = reinterpret_cast<const float4*>(X + (size_t)b * NROW * 16);
  const int q = tid & 3;      // 640 % 4 == 0: constant per thread
  float4 s4 = make_float4(0.f, 0.f, 0.f, 0.f);
  float mloc = 0.f;
#pragma unroll 4
  for (int idx = tid; idx < NROW * 4; idx += THREADS) {
    int n = idx >> 2;
    float4 v = Xb[idx];
    __half2 h01 = __floats2half2_rn(v.x, v.y);
    __half2 h23 = __floats2half2_rn(v.z, v.w);
    ull packed;
    asm("mov.b64 %0, {%1, %2};" : "=l"(packed)
        : "r"(*(uint*)&h01), "r"(*(uint*)&h23));
    *reinterpret_cast<ull*>(&sm->xs[n * XSH + q * 4]) = packed;
    s4.x += v.x; s4.y += v.y; s4.z += v.z; s4.w += v.w;
    float qd = v.x * v.x + v.y * v.y + v.z * v.z + v.w * v.w;
    qd += __shfl_xor_sync(0xffffffffu, qd, 1);
    qd += __shfl_xor_sync(0xffffffffu, qd, 2);
    mloc = fmaxf(mloc, qd);
  }
#pragma unroll
  for (int off = 4; off < 32; off <<= 1) {
    s4.x += __shfl_xor_sync(0xffffffffu, s4.x, off);
    s4.y += __shfl_xor_sync(0xffffffffu, s4.y, off);
    s4.z += __shfl_xor_sync(0xffffffffu, s4.z, off);
    s4.w += __shfl_xor_sync(0xffffffffu, s4.w, off);
    mloc = fmaxf(mloc, __shfl_xor_sync(0xffffffffu, mloc, off));
  }
  if (lane < 4) *reinterpret_cast<float4*>(&sm->wpart[w][lane * 4]) = s4;
  if (lane == 0) sm->wmax[w] = mloc;

  // ---- W slices in two layouts (fp32, epilogue only) ----
#pragma unroll 1
  for (int idx2 = tid; idx2 < 4096; idx2 += THREADS) {
    int ml = idx2 >> 8, d = (idx2 >> 4) & 15, c = idx2 & 15;
    float val = Wg[d * 512 + (m0 + ml) * 16 + c];
    sm->Wdc[idx2] = val;
    sm->Wcd[ml * 256 + c * 16 + d] = val;
  }
  __syncthreads();

  if (tid < 16) {
    float s = 0.f;
#pragma unroll
    for (int ww = 0; ww < NWARP; ++ww) s += sm->wpart[ww][tid];
    sm->sumx[tid] = s;
  }
  if (tid == 16) {
    float mx = 0.f;
#pragma unroll
    for (int ww = 0; ww < NWARP; ++ww) mx = fmaxf(mx, sm->wmax[ww]);
    sm->mxnorm = sqrtf(mx);
  }
  __syncthreads();

  const int gid = lane >> 2, tig = lane & 3;
  const uint xsb = (uint)__cvta_generic_to_shared(sm->xs);
  // ldmatrix.x4.trans lane->address map: 4 8x8 tiles of X[nb..nb+15][0..15]
  const int lrow = (lane & 7) + ((lane >> 4) << 3);
  const int lcol = (lane & 8) ? 16 : 0;
  // 128 ksteps over 20 warps: first 8 warps take 7, remaining 12 take 6
  const int ks0 = (w < 8) ? 7 * w : 56 + 6 * (w - 8);
  const int nks = (w < 8) ? 7 : 6;

  for (int it = 0; it < 3; ++it) {
    if (it > 0) {
      // ---- tensor-core pass: each warp does nks*16 rows x all 16 caps ----
      uint pah[4], pal[4];
      pah[0] = *(const uint*)&sm->Pt_hi[gid][2 * tig];
      pah[1] = *(const uint*)&sm->Pt_hi[gid + 8][2 * tig];
      pah[2] = *(const uint*)&sm->Pt_hi[gid][2 * tig + 8];
      pah[3] = *(const uint*)&sm->Pt_hi[gid + 8][2 * tig + 8];
      pal[0] = *(const uint*)&sm->Pt_lo[gid][2 * tig];
      pal[1] = *(const uint*)&sm->Pt_lo[gid + 8][2 * tig];
      pal[2] = *(const uint*)&sm->Pt_lo[gid][2 * tig + 8];
      pal[3] = *(const uint*)&sm->Pt_lo[gid + 8][2 * tig + 8];
      const float iA = 15.f - sm->bnd[gid];
      const float iB = 15.f - sm->bnd[gid + 8];
      float y00 = 0.f, y01 = 0.f, y02 = 0.f, y03 = 0.f;
      float y10 = 0.f, y11 = 0.f, y12 = 0.f, y13 = 0.f;
      float z0 = 0.f, z1 = 0.f;
      const int nb0 = ks0 * 16;
      const uint lm0 = xsb + (uint)(nb0 + lrow) * 48 + lcol;

#pragma unroll 2
      for (int ks = 0; ks < nks; ++ks) {
        const int nb = nb0 + ks * 16;
        // GEMM1 B-frags: X rows (plain b32 reads, conflict-free)
        const uint* xr0 = (const uint*)&sm->xs[(nb + gid) * XSH + 2 * tig];
        const uint* xr1 = (const uint*)&sm->xs[(nb + 8 + gid) * XSH + 2 * tig];
        uint b00 = xr0[0], b01 = xr0[4];
        uint b10 = xr1[0], b11 = xr1[4];
        // GEMM1: logits (caps x n), bnd+15 folded into C init, P = hi + lo
        float c00 = iA, c01 = iA, c02 = iB, c03 = iB;
        hmma(c00, c01, c02, c03, pah[0], pah[1], pah[2], pah[3], b00, b01);
        hmma(c00, c01, c02, c03, pal[0], pal[1], pal[2], pal[3], b00, b01);
        float c10 = iA, c11 = iA, c12 = iB, c13 = iB;
        hmma(c10, c11, c12, c13, pah[0], pah[1], pah[2], pah[3], b10, b11);
        hmma(c10, c11, c12, c13, pal[0], pal[1], pal[2], pal[3], b10, b11);
        // softmax numerators
        float e0 = ex2f(c00), e1 = ex2f(c01), e2 = ex2f(c02), e3 = ex2f(c03);
        float e4 = ex2f(c10), e5 = ex2f(c11), e6 = ex2f(c12), e7 = ex2f(c13);
        z0 += (e0 + e1) + (e4 + e5);
        z1 += (e2 + e3) + (e6 + e7);
        // C-frag -> A-frag of GEMM2 (exact layout match, just cvt to fp16)
        uint a0 = cvt2h(e1, e0), a1 = cvt2h(e3, e2);
        uint a2 = cvt2h(e5, e4), a3 = cvt2h(e7, e6);
        // GEMM2: y[caps,d] += E(caps x 16n) @ X(16n x 16d)
        uint r0, r1, r2, r3;
        ldsm4t(r0, r1, r2, r3, lm0 + (uint)(ks * 16 * 48));
        hmma(y00, y01, y02, y03, a0, a1, a2, a3, r0, r2);   // d 0-7
        hmma(y10, y11, y12, y13, a0, a1, a2, a3, r1, r3);   // d 8-15
      }
      // Z: quad reduce (4 lanes share each cap row)
      z0 += __shfl_xor_sync(0xffffffffu, z0, 1);
      z0 += __shfl_xor_sync(0xffffffffu, z0, 2);
      z1 += __shfl_xor_sync(0xffffffffu, z1, 1);
      z1 += __shfl_xor_sync(0xffffffffu, z1, 2);
      if (tig == 0) {
        sm->partZ[w][gid] = z0;
        sm->partZ[w][gid + 8] = z1;
      }
      *(float2*)&sm->party[w][gid][2 * tig]         = make_float2(y00, y01);
      *(float2*)&sm->party[w][gid + 8][2 * tig]     = make_float2(y02, y03);
      *(float2*)&sm->party[w][gid][2 * tig + 8]     = make_float2(y10, y11);
      *(float2*)&sm->party[w][gid + 8][2 * tig + 8] = make_float2(y12, y13);
      __syncthreads();

      // fold warp partials
      if (tid < 256) {
        const int cap = tid >> 4, d = tid & 15;
        float acc = 0.f;
#pragma unroll
        for (int ww = 0; ww < NWARP; ++ww) acc += sm->party[ww][cap][d];
        sm->yfull[cap][d] = acc;
      } else if (tid < 272) {
        const int cap = tid - 256;
        float acc = 0.f;
#pragma unroll
        for (int ww = 0; ww < NWARP; ++ww) acc += sm->partZ[ww][cap];
        sm->Zfull[cap] = acc;
      }
    }
    __syncthreads();

    // ---- epilogue: s = yW/Z, squash, Pacc += log2e W v, Pt hi/lo, bound ----
    if (w < 8) {
      const int ml  = w * 2 + (lane >> 4);
      const int idx = lane & 15;
      float Z = (it == 0) ? 2048.f : sm->Zfull[ml];
      float s = 0.f;
#pragma unroll
      for (int d = 0; d < 16; ++d) {
        float yv = (it == 0) ? sm->sumx[d] : sm->yfull[ml][d];
        s += yv * sm->Wdc[(ml * 16 + d) * 16 + idx];
      }
      s *= (1.f / Z);
      float nsq = s * s;
#pragma unroll
      for (int off = 1; off < 16; off <<= 1) nsq += __shfl_xor_sync(0xffffffffu, nsq, off);
      float norm = sqrtf(nsq);
      float fac  = nsq / ((1.f + nsq) * (norm + 1e-7f));
      float v    = s * fac;
      if (it == 2) {
        Y[(size_t)b * 512 + (m0 + ml) * 16 + idx] = v;
      } else {
        sm->vbuf[ml][idx] = v;
        __syncwarp();
        float pd = 0.f;
#pragma unroll
        for (int c = 0; c < 16; ++c)
          pd += sm->Wcd[(ml * 16 + c) * 16 + idx] * sm->vbuf[ml][c];
        float pn = sm->Pacc[ml][idx] + LOG2E * pd;
        sm->Pacc[ml][idx] = pn;
        __half h = __float2half_rn(pn);
        sm->Pt_hi[ml][idx] = h;
        sm->Pt_lo[ml][idx] = __float2half_rn(pn - __half2float(h));
        float cn = pn * pn;
#pragma unroll
        for (int off = 1; off < 16; off <<= 1) cn += __shfl_xor_sync(0xffffffffu, cn, off);
        if (idx == 0) sm->bnd[ml] = sqrtf(cn) * sm->mxnorm;
      }
    }
    __syncthreads();
  }
}

extern "C" void kernel_launch(void* const* d_in, const int* in_sizes, int n_in,
                              void* d_out, int out_size) {
  (void)in_sizes; (void)n_in; (void)out_size;
  const float* X  = (const float*)d_in[0];   // inputs (64, 2048, 16)
  const float* Wg = (const float*)d_in[1];   // W (16, 32, 16)
  float* Y = (float*)d_out;                  // v (64, 32, 16)
  cudaFuncSetAttribute(caps_routing_kernel,
                       cudaFuncAttributeMaxDynamicSharedMemorySize, (int)sizeof(Smem));
  caps_routing_kernel<<<128, THREADS, sizeof(Smem)>>>(X, Wg, Y);
}

// round 17
// speedup vs baseline: 1.1855x; 1.1855x over previous
#include <cuda_runtime.h>
#include <cuda_fp16.h>
#include <cstdint>

// CapsuleLayer dynamic routing, algebraically collapsed (u_hat never built):
//   L[n,m] = x[n,:] @ Pacc[:,m]  (Pacc = log2e * accum W@v, so exp == EX2)
//   E = 2^(L - bnd + 15), Z[m] = sum_n E, y[m,:] = E^T x
//   s = (y/Z) W, v = squash(s), Pacc += log2e W v
// bnd = Cauchy-Schwarz bound ||Pacc_col||*max||x_n||; +15 shift keeps fp16 E
// in range. Both GEMMs on tensor cores (mma.m16n8k16, C->A fragment reuse,
// P split hi+lo fp16).
// R17 = R13 champion + Z-as-GEMM: x padding columns hold {1,0,...}, a third
//       GEMM2 HMMA accumulates Z in its col-16 output (one ldmatrix.x2 extra),
//       deleting 8 FADD/kstep and the 4-shfl Z reduction.

#define NROW    2048
#define XSH     24            // halves per x row (48B); cols 16-23 = {1,0,...}
#define THREADS 512
#define LOG2E   1.4426950408889634f

typedef unsigned long long ull;
typedef unsigned int uint;

struct Smem {
  __half xs[NROW * XSH];        // fp16 x rows, 96KB
  float  Wdc[4096];             // [ml][d][c]
  float  Wcd[4096];             // [ml][c][d]
  float  Pacc[16][16];          // fp32 master (log2e-scaled)
  __half Pt_hi[16][XSH];        // P^T fp16 high part  [cap][d]
  __half Pt_lo[16][XSH];        // P^T fp16 residual
  float  party[16][16][16];     // [warp][cap][d] partial y
  float  partZ[16][16];         // [warp][cap]
  float  yfull[16][16];
  float  Zfull[16];
  float  wpart[16][16];
  float  wmax[16];
  float  sumx[16];
  float  vbuf[16][16];
  float  bnd[16];               // log2-domain bound per cap
  float  mxnorm;
  float  pad[3];
};

__device__ __forceinline__ float ex2f(float x) {
  float r; asm("ex2.approx.f32 %0, %1;" : "=f"(r) : "f"(x)); return r;
}
__device__ __forceinline__ uint cvt2h(float hi, float lo) {
  uint r; asm("cvt.rn.f16x2.f32 %0, %1, %2;" : "=r"(r) : "f"(hi), "f"(lo)); return r;
}
__device__ __forceinline__ void hmma(float& d0, float& d1, float& d2, float& d3,
                                     uint a0, uint a1, uint a2, uint a3,
                                     uint b0, uint b1) {
  asm("mma.sync.aligned.m16n8k16.row.col.f32.f16.f16.f32 "
      "{%0,%1,%2,%3}, {%4,%5,%6,%7}, {%8,%9}, {%0,%1,%2,%3};"
      : "+f"(d0), "+f"(d1), "+f"(d2), "+f"(d3)
      : "r"(a0), "r"(a1), "r"(a2), "r"(a3), "r"(b0), "r"(b1));
}
__device__ __forceinline__ void ldsm4t(uint& r0, uint& r1, uint& r2, uint& r3,
                                       uint addr) {
  asm volatile("ldmatrix.sync.aligned.m8n8.x4.trans.shared.b16 {%0,%1,%2,%3}, [%4];"
               : "=r"(r0), "=r"(r1), "=r"(r2), "=r"(r3) : "r"(addr));
}
__device__ __forceinline__ void ldsm2t(uint& r0, uint& r1, uint addr) {
  asm volatile("ldmatrix.sync.aligned.m8n8.x2.trans.shared.b16 {%0,%1}, [%2];"
               : "=r"(r0), "=r"(r1) : "r"(addr));
}

__global__ void __launch_bounds__(THREADS, 1)
caps_routing_kernel(const float* __restrict__ X, const float* __restrict__ Wg,
                    float* __restrict__ Y) {
  extern __shared__ char smraw[];
  Smem* sm = reinterpret_cast<Smem*>(smraw);
  const int tid  = threadIdx.x;
  const int lane = tid & 31;
  const int w    = tid >> 5;
  const int b    = blockIdx.x >> 1;
  const int m0   = (blockIdx.x & 1) * 16;

  if (tid < 256) ((float*)sm->Pacc)[tid] = 0.f;
  if (tid >= 256 && tid < 272) sm->bnd[tid - 256] = 0.f;

  // ---- Load x tile; fp16 into smem; fold in column sums + max row norm ----
  const float4* Xb = reinterpret_cast<const float4*>(X + (size_t)b * NROW * 16);
  const int q = tid & 3;
  float4 s4 = make_float4(0.f, 0.f, 0.f, 0.f);
  float mloc = 0.f;
#pragma unroll
  for (int i = 0; i < 16; ++i) {
    int idx = tid + THREADS * i;
    int n = idx >> 2;
    float4 v = Xb[idx];
    __half2 h01 = __floats2half2_rn(v.x, v.y);
    __half2 h23 = __floats2half2_rn(v.z, v.w);
    ull packed;
    asm("mov.b64 %0, {%1, %2};" : "=l"(packed)
        : "r"(*(uint*)&h01), "r"(*(uint*)&h23));
    *reinterpret_cast<ull*>(&sm->xs[n * XSH + q * 4]) = packed;
    s4.x += v.x; s4.y += v.y; s4.z += v.z; s4.w += v.w;
    float qd = v.x * v.x + v.y * v.y + v.z * v.z + v.w * v.w;
    qd += __shfl_xor_sync(0xffffffffu, qd, 1);
    qd += __shfl_xor_sync(0xffffffffu, qd, 2);
    mloc = fmaxf(mloc, qd);
  }
  // ones column (col 16) + zero padding (cols 17-23) for the Z GEMM
  {
    const uint one0 = 0x00003c00u;   // {1.0h, 0.0h}
    uint4 ones = make_uint4(one0, 0u, 0u, 0u);
#pragma unroll
    for (int r = 0; r < 4; ++r) {
      int n = tid + THREADS * r;
      *reinterpret_cast<uint4*>(&sm->xs[n * XSH + 16]) = ones;
    }
  }
#pragma unroll
  for (int off = 4; off < 32; off <<= 1) {
    s4.x += __shfl_xor_sync(0xffffffffu, s4.x, off);
    s4.y += __shfl_xor_sync(0xffffffffu, s4.y, off);
    s4.z += __shfl_xor_sync(0xffffffffu, s4.z, off);
    s4.w += __shfl_xor_sync(0xffffffffu, s4.w, off);
    mloc = fmaxf(mloc, __shfl_xor_sync(0xffffffffu, mloc, off));
  }
  if (lane < 4) *reinterpret_cast<float4*>(&sm->wpart[w][lane * 4]) = s4;
  if (lane == 0) sm->wmax[w] = mloc;

  // ---- W slices in two layouts (fp32, epilogue only) ----
#pragma unroll
  for (int i = 0; i < 8; ++i) {
    int idx2 = tid + THREADS * i;
    int ml = idx2 >> 8, d = (idx2 >> 4) & 15, c = idx2 & 15;
    float val = Wg[d * 512 + (m0 + ml) * 16 + c];
    sm->Wdc[idx2] = val;
    sm->Wcd[ml * 256 + c * 16 + d] = val;
  }
  __syncthreads();

  if (tid < 16) {
    float s = 0.f;
#pragma unroll
    for (int ww = 0; ww < 16; ++ww) s += sm->wpart[ww][tid];
    sm->sumx[tid] = s;
  }
  if (tid == 16) {
    float mx = 0.f;
#pragma unroll
    for (int ww = 0; ww < 16; ++ww) mx = fmaxf(mx, sm->wmax[ww]);
    sm->mxnorm = sqrtf(mx);
  }
  __syncthreads();

  const int gid = lane >> 2, tig = lane & 3;
  const uint xsb = (uint)__cvta_generic_to_shared(sm->xs);
  // ldmatrix.x4.trans lane->address map: 4 8x8 tiles of X[nb..nb+15][0..15]
  const int lrow = (lane & 7) + ((lane >> 4) << 3);
  const int lcol = (lane & 8) ? 16 : 0;
  // ldmatrix.x2.trans lane map (lanes 0-15 used): rows 0..15, cols 16-23 (32B)
  const int lrow2 = (lane & 7) + (((lane >> 3) & 1) << 3);

  for (int it = 0; it < 3; ++it) {
    if (it > 0) {
      // ---- tensor-core pass: each warp does 128 rows x all 16 caps ----
      uint pah[4], pal[4];
      pah[0] = *(const uint*)&sm->Pt_hi[gid][2 * tig];
      pah[1] = *(const uint*)&sm->Pt_hi[gid + 8][2 * tig];
      pah[2] = *(const uint*)&sm->Pt_hi[gid][2 * tig + 8];
      pah[3] = *(const uint*)&sm->Pt_hi[gid + 8][2 * tig + 8];
      pal[0] = *(const uint*)&sm->Pt_lo[gid][2 * tig];
      pal[1] = *(const uint*)&sm->Pt_lo[gid + 8][2 * tig];
      pal[2] = *(const uint*)&sm->Pt_lo[gid][2 * tig + 8];
      pal[3] = *(const uint*)&sm->Pt_lo[gid + 8][2 * tig + 8];
      const float iA = 15.f - sm->bnd[gid];
      const float iB = 15.f - sm->bnd[gid + 8];
      float y00 = 0.f, y01 = 0.f, y02 = 0.f, y03 = 0.f;
      float y10 = 0.f, y11 = 0.f, y12 = 0.f, y13 = 0.f;
      float yz0 = 0.f, yz1 = 0.f, yz2 = 0.f, yz3 = 0.f;   // col16 of yz0/yz2 = Z
      const int nb0 = w * 128;
      const uint lm0 = xsb + (uint)(nb0 + lrow) * 48 + lcol;
      const uint lz0 = xsb + (uint)(nb0 + lrow2) * 48 + 32;

#pragma unroll 2
      for (int ks = 0; ks < 8; ++ks) {
        const int nb = nb0 + ks * 16;
        // GEMM1 B-frags: X rows (plain b32 reads, conflict-free)
        const uint* xr0 = (const uint*)&sm->xs[(nb + gid) * XSH + 2 * tig];
        const uint* xr1 = (const uint*)&sm->xs[(nb + 8 + gid) * XSH + 2 * tig];
        uint b00 = xr0[0], b01 = xr0[4];
        uint b10 = xr1[0], b11 = xr1[4];
        // GEMM1: logits (caps x n), bnd+15 folded into C init, P = hi + lo
        float c00 = iA, c01 = iA, c02 = iB, c03 = iB;
        hmma(c00, c01, c02, c03, pah[0], pah[1], pah[2], pah[3], b00, b01);
        hmma(c00, c01, c02, c03, pal[0], pal[1], pal[2], pal[3], b00, b01);
        float c10 = iA, c11 = iA, c12 = iB, c13 = iB;
        hmma(c10, c11, c12, c13, pah[0], pah[1], pah[2], pah[3], b10, b11);
        hmma(c10, c11, c12, c13, pal[0], pal[1], pal[2], pal[3], b10, b11);
        // softmax numerators
        float e0 = ex2f(c00), e1 = ex2f(c01), e2 = ex2f(c02), e3 = ex2f(c03);
        float e4 = ex2f(c10), e5 = ex2f(c11), e6 = ex2f(c12), e7 = ex2f(c13);
        // C-frag -> A-frag of GEMM2 (exact layout match, just cvt to fp16)
        uint a0 = cvt2h(e1, e0), a1 = cvt2h(e3, e2);
        uint a2 = cvt2h(e5, e4), a3 = cvt2h(e7, e6);
        // GEMM2: y[caps,d] += E(caps x 16n) @ X(16n x 16d); Z via ones col 16
        uint r0, r1, r2, r3, rz0, rz1;
        ldsm4t(r0, r1, r2, r3, lm0 + (uint)(ks * 16 * 48));
        ldsm2t(rz0, rz1, lz0 + (uint)(ks * 16 * 48));
        hmma(y00, y01, y02, y03, a0, a1, a2, a3, r0, r2);   // d 0-7
        hmma(y10, y11, y12, y13, a0, a1, a2, a3, r1, r3);   // d 8-15
        hmma(yz0, yz1, yz2, yz3, a0, a1, a2, a3, rz0, rz1); // d 16 = Z
      }
      if (tig == 0) {
        sm->partZ[w][gid]     = yz0;   // col16 for cap row gid
        sm->partZ[w][gid + 8] = yz2;   // col16 for cap row gid+8
      }
      *(float2*)&sm->party[w][gid][2 * tig]         = make_float2(y00, y01);
      *(float2*)&sm->party[w][gid + 8][2 * tig]     = make_float2(y02, y03);
      *(float2*)&sm->party[w][gid][2 * tig + 8]     = make_float2(y10, y11);
      *(float2*)&sm->party[w][gid + 8][2 * tig + 8] = make_float2(y12, y13);
      __syncthreads();

      // fold 16 warp partials
      if (tid < 256) {
        const int cap = tid >> 4, d = tid & 15;
        float acc = 0.f;
#pragma unroll
        for (int ww = 0; ww < 16; ++ww) acc += sm->party[ww][cap][d];
        sm->yfull[cap][d] = acc;
      } else if (tid < 272) {
        const int cap = tid - 256;
        float acc = 0.f;
#pragma unroll
        for (int ww = 0; ww < 16; ++ww) acc += sm->partZ[ww][cap];
        sm->Zfull[cap] = acc;
      }
    }
    __syncthreads();

    // ---- epilogue: s = yW/Z, squash, Pacc += log2e W v, Pt hi/lo, bound ----
    if (w < 8) {
      const int ml  = w * 2 + (lane >> 4);
      const int idx = lane & 15;
      float Z = (it == 0) ? 2048.f : sm->Zfull[ml];
      float s = 0.f;
#pragma unroll
      for (int d = 0; d < 16; ++d) {
        float yv = (it == 0) ? sm->sumx[d] : sm->yfull[ml][d];
        s += yv * sm->Wdc[(ml * 16 + d) * 16 + idx];
      }
      s *= (1.f / Z);
      float nsq = s * s;
#pragma unroll
      for (int off = 1; off < 16; off <<= 1) nsq += __shfl_xor_sync(0xffffffffu, nsq, off);
      float norm = sqrtf(nsq);
      float fac  = nsq / ((1.f + nsq) * (norm + 1e-7f));
      float v    = s * fac;
      if (it == 2) {
        Y[(size_t)b * 512 + (m0 + ml) * 16 + idx] = v;
      } else {
        sm->vbuf[ml][idx] = v;
        __syncwarp();
        float pd = 0.f;
#pragma unroll
        for (int c = 0; c < 16; ++c)
          pd += sm->Wcd[(ml * 16 + c) * 16 + idx] * sm->vbuf[ml][c];
        float pn = sm->Pacc[ml][idx] + LOG2E * pd;
        sm->Pacc[ml][idx] = pn;
        __half h = __float2half_rn(pn);
        sm->Pt_hi[ml][idx] = h;
        sm->Pt_lo[ml][idx] = __float2half_rn(pn - __half2float(h));
        float cn = pn * pn;
#pragma unroll
        for (int off = 1; off < 16; off <<= 1) cn += __shfl_xor_sync(0xffffffffu, cn, off);
        if (idx == 0) sm->bnd[ml] = sqrtf(cn) * sm->mxnorm;
      }
    }
    __syncthreads();
  }
}

extern "C" void kernel_launch(void* const* d_in, const int* in_sizes, int n_in,
                              void* d_out, int out_size) {
  (void)in_sizes; (void)n_in; (void)out_size;
  const float* X  = (const float*)d_in[0];   // inputs (64, 2048, 16)
  const float* Wg = (const float*)d_in[1];   // W (16, 32, 16)
  float* Y = (float*)d_out;                  // v (64, 32, 16)
  cudaFuncSetAttribute(caps_routing_kernel,
                       cudaFuncAttributeMaxDynamicSharedMemorySize, (int)sizeof(Smem));
  caps_routing_kernel<<<128, THREADS, sizeof(Smem)>>>(X, Wg, Y);
}